// round 16
// baseline (speedup 1.0000x reference)
#include <cuda_runtime.h>
#include <cstdint>

#define NN 100000
#define EE 1600000
#define DD 128
#define MAXDEG 96
#define OVF_CAP 8192
#define MROWS 64

// Scratch (allocation-free: device globals)
__device__ float g_aggr[(size_t)NN * DD];
__device__ int g_fill[NN];
__device__ int2 g_perm2[(size_t)NN * MAXDEG];  // {edge, src}
__device__ int g_ovf[OVF_CAP];
__device__ int g_ovf_cnt;

// ---------------------------------------------------------------------------
// Slot binning
// ---------------------------------------------------------------------------
__global__ void zero_kernel() {
    int i = blockIdx.x * blockDim.x + threadIdx.x;
    if (i < NN) g_fill[i] = 0;
    if (i == 0) g_ovf_cnt = 0;
}

__global__ void fill_kernel(const int* __restrict__ ei) {
    int base = (blockIdx.x * blockDim.x + threadIdx.x) * 8;
    #pragma unroll
    for (int u = 0; u < 8; u++) {
        int e = base + u;
        if (e < EE) {
            int dst = __ldg(ei + EE + e);
            int src = __ldg(ei + e);
            int pos = atomicAdd(&g_fill[dst], 1);
            if (pos < MAXDEG) {
                g_perm2[(size_t)dst * MAXDEG + pos] = make_int2(e, src);
            } else {
                int o = atomicAdd(&g_ovf_cnt, 1);
                if (o < OVF_CAP) g_ovf[o] = e;
            }
        }
    }
}

// ---------------------------------------------------------------------------
// Aggregation: warp per node. Unroll-4, 5 CTAs/SM (75% DRAM measured).
// ---------------------------------------------------------------------------
__device__ __forceinline__ void stcs4(float4* p, float4 v) {
    asm volatile("st.global.cs.v4.f32 [%0], {%1, %2, %3, %4};"
                 :: "l"(p), "f"(v.x), "f"(v.y), "f"(v.z), "f"(v.w) : "memory");
}

__global__ __launch_bounds__(256, 5) void aggr_kernel(const float* __restrict__ x,
                                                      const float* __restrict__ ea) {
    int node = blockIdx.x * 8 + (threadIdx.x >> 5);
    int lane = threadIdx.x & 31;
    int cnt = min(g_fill[node], MAXDEG);
    const int2* slots = g_perm2 + (size_t)node * MAXDEG;
    float4 acc = make_float4(0.f, 0.f, 0.f, 0.f);

    for (int base = 0; base < cnt; base += 32) {
        int m = min(32, cnt - base);
        int2 es = make_int2(0, 0);
        if (lane < m) es = __ldcs(&slots[base + lane]);
        int t = 0;
        for (; t + 4 <= m; t += 4) {
            int eu[4], su[4];
            #pragma unroll
            for (int u = 0; u < 4; u++) {
                eu[u] = __shfl_sync(0xffffffffu, es.x, t + u);
                su[u] = __shfl_sync(0xffffffffu, es.y, t + u);
            }
            float4 xv[4], av[4];
            #pragma unroll
            for (int u = 0; u < 4; u++) {
                xv[u] = __ldg(reinterpret_cast<const float4*>(x) + su[u] * 32 + lane);
                av[u] = __ldcs(reinterpret_cast<const float4*>(ea) + eu[u] * 32 + lane);
            }
            #pragma unroll
            for (int u = 0; u < 4; u++) {
                acc.x += fmaxf(xv[u].x + av[u].x, 0.f);
                acc.y += fmaxf(xv[u].y + av[u].y, 0.f);
                acc.z += fmaxf(xv[u].z + av[u].z, 0.f);
                acc.w += fmaxf(xv[u].w + av[u].w, 0.f);
            }
        }
        for (; t < m; t++) {
            int et = __shfl_sync(0xffffffffu, es.x, t);
            int st = __shfl_sync(0xffffffffu, es.y, t);
            float4 xr = __ldg(reinterpret_cast<const float4*>(x) + st * 32 + lane);
            float4 ar = __ldcs(reinterpret_cast<const float4*>(ea) + et * 32 + lane);
            acc.x += fmaxf(xr.x + ar.x, 0.f);
            acc.y += fmaxf(xr.y + ar.y, 0.f);
            acc.z += fmaxf(xr.z + ar.z, 0.f);
            acc.w += fmaxf(xr.w + ar.w, 0.f);
        }
    }
    stcs4(reinterpret_cast<float4*>(g_aggr) + node * 32 + lane, acc);
}

// ---------------------------------------------------------------------------
// mma.sync helpers (tf32 m16n8k8, family-portable PTX)
// ---------------------------------------------------------------------------
__device__ __forceinline__ void mma_tf32(float c[4], const unsigned a[4],
                                         unsigned b0, unsigned b1) {
    asm volatile(
        "mma.sync.aligned.m16n8k8.row.col.f32.tf32.tf32.f32 "
        "{%0,%1,%2,%3}, {%4,%5,%6,%7}, {%8,%9}, {%0,%1,%2,%3};"
        : "+f"(c[0]), "+f"(c[1]), "+f"(c[2]), "+f"(c[3])
        : "r"(a[0]), "r"(a[1]), "r"(a[2]), "r"(a[3]), "r"(b0), "r"(b1));
}
__device__ __forceinline__ void split_tf32(float v, unsigned& hi, unsigned& lo) {
    asm("cvt.rna.tf32.f32 %0, %1;" : "=r"(hi) : "f"(v));
    float r = v - __uint_as_float(hi);
    asm("cvt.rna.tf32.f32 %0, %1;" : "=r"(lo) : "f"(r));
}

// ---------------------------------------------------------------------------
// Tensor-core fused 2-layer MLP. 64-row tile, 256 threads (8 warps), 2 CTAs/SM.
// smem: AsF = A fragments [4 mb][16 kb][32 lane][4 reg] f32 (32KB)
//       WsF = W fragments [16 nb][16 kb][32 lane][2 reg] f32 (64KB)
// Warp (mb = wid&3, nh = wid>>2) computes rows mb*16..+15, cols nh*64..+63.
// 3xTF32: D += Ahi*Bhi + Alo*Bhi + Ahi*Blo.
// ---------------------------------------------------------------------------
__global__ __launch_bounds__(256, 2) void mlp_tc(
    const float* __restrict__ A,
    const float* __restrict__ X,
    const float* __restrict__ epsp,
    const float* __restrict__ W1,
    const float* __restrict__ b1,
    const float* __restrict__ W2,
    const float* __restrict__ b2,
    float* __restrict__ out,
    const int* __restrict__ ei,
    const float* __restrict__ ea,
    int nrows) {
    extern __shared__ float smem[];
    float* AsF = smem;                  // 8192 floats
    float* WsF = smem + 4 * 16 * 128;   // 16384 floats

    int tid = threadIdx.x;
    int row0 = blockIdx.x * MROWS;
    float epsv = 1.0f + __ldg(epsp);
    int nov = g_ovf_cnt;
    if (nov > OVF_CAP) nov = OVF_CAP;

    // ---- Stage W1 into fragment layout ----
    #pragma unroll
    for (int t = 0; t < 16; t++) {
        int i = tid + t * 256;          // 4096 float4
        int k = i >> 5, n4 = i & 31;
        float4 w = __ldg(reinterpret_cast<const float4*>(W1) + i);
        int kb = k >> 3;
        int reg = ((k & 7) >= 4) ? 1 : 0;
        int lt = k & 3;
        #pragma unroll
        for (int j = 0; j < 4; j++) {
            int n = n4 * 4 + j;
            int nb = n >> 3, nl = n & 7;
            float val = (j == 0) ? w.x : (j == 1) ? w.y : (j == 2) ? w.z : w.w;
            WsF[(((nb * 16 + kb) * 32) + nl * 4 + lt) * 2 + reg] = val;
        }
    }
    // ---- Stage A' = (1+eps)x + aggr into fragment layout ----
    #pragma unroll
    for (int t = 0; t < 8; t++) {
        int i = tid + t * 256;          // 2048 float4
        int row = i >> 5, c4 = i & 31;
        int gr = row0 + row;
        float4 v = make_float4(0.f, 0.f, 0.f, 0.f);
        if (gr < nrows) {
            v = __ldcs(reinterpret_cast<const float4*>(A) + gr * 32 + c4);
            float4 xv = __ldg(reinterpret_cast<const float4*>(X) + gr * 32 + c4);
            v.x += epsv * xv.x;
            v.y += epsv * xv.y;
            v.z += epsv * xv.z;
            v.w += epsv * xv.w;
            if (nov > 0) {  // overflow fixup (empty for this dataset)
                for (int o = 0; o < nov; o++) {
                    int e = g_ovf[o];
                    if (__ldg(ei + EE + e) == gr) {
                        int src = __ldg(ei + e);
                        float4 xs = __ldg(reinterpret_cast<const float4*>(X) + src * 32 + c4);
                        float4 as = __ldg(reinterpret_cast<const float4*>(ea) + e * 32 + c4);
                        v.x += fmaxf(xs.x + as.x, 0.f);
                        v.y += fmaxf(xs.y + as.y, 0.f);
                        v.z += fmaxf(xs.z + as.z, 0.f);
                        v.w += fmaxf(xs.w + as.w, 0.f);
                    }
                }
            }
        }
        int mb = row >> 4, r16 = row & 15;
        int g = r16 & 7, hi8 = r16 >> 3;
        int kb = c4 >> 1;
        int regbase = hi8 + ((c4 & 1) ? 2 : 0);
        #pragma unroll
        for (int j = 0; j < 4; j++) {
            float val = (j == 0) ? v.x : (j == 1) ? v.y : (j == 2) ? v.z : v.w;
            AsF[(((mb * 16 + kb) * 32) + g * 4 + j) * 4 + regbase] = val;
        }
    }
    __syncthreads();

    int wid = tid >> 5, lane = tid & 31;
    int mb = wid & 3, nh = wid >> 2;
    int g = lane >> 2, tq = lane & 3;

    float c[8][4];
    #pragma unroll
    for (int n = 0; n < 8; n++)
        #pragma unroll
        for (int j = 0; j < 4; j++) c[n][j] = 0.f;

    // ---- Layer 1 ----
    #pragma unroll 4
    for (int kb = 0; kb < 16; kb++) {
        float4 af = *reinterpret_cast<const float4*>(&AsF[((mb * 16 + kb) * 32 + lane) * 4]);
        unsigned ah[4], al[4];
        split_tf32(af.x, ah[0], al[0]);
        split_tf32(af.y, ah[1], al[1]);
        split_tf32(af.z, ah[2], al[2]);
        split_tf32(af.w, ah[3], al[3]);
        #pragma unroll
        for (int nbl = 0; nbl < 8; nbl++) {
            int nb = nh * 8 + nbl;
            float2 bf = *reinterpret_cast<const float2*>(&WsF[((nb * 16 + kb) * 32 + lane) * 2]);
            unsigned bh0, bl0, bh1, bl1;
            split_tf32(bf.x, bh0, bl0);
            split_tf32(bf.y, bh1, bl1);
            mma_tf32(c[nbl], ah, bh0, bh1);
            mma_tf32(c[nbl], al, bh0, bh1);
            mma_tf32(c[nbl], ah, bl0, bl1);
        }
    }
    __syncthreads();

    // ---- Epilogue 1: h = relu(c + b1) restaged to A-frag layout; W2 -> WsF ----
    #pragma unroll
    for (int nbl = 0; nbl < 8; nbl++) {
        int nb = nh * 8 + nbl;
        float2 bv = __ldg(reinterpret_cast<const float2*>(b1 + nb * 8 + 2 * tq));
        float h00 = fmaxf(c[nbl][0] + bv.x, 0.f);  // (row g,   n 2t)
        float h01 = fmaxf(c[nbl][1] + bv.y, 0.f);  // (row g,   n 2t+1)
        float h10 = fmaxf(c[nbl][2] + bv.x, 0.f);  // (row g+8, n 2t)
        float h11 = fmaxf(c[nbl][3] + bv.y, 0.f);  // (row g+8, n 2t+1)
        int n0 = 2 * tq, n1 = 2 * tq + 1;
        int l0 = g * 4 + (n0 & 3), r0 = (n0 >= 4) ? 2 : 0;
        int l1 = g * 4 + (n1 & 3), r1 = (n1 >= 4) ? 2 : 0;
        float* basep = &AsF[((mb * 16 + nb) * 32) * 4];  // kb2 = nb
        basep[l0 * 4 + r0] = h00;
        basep[l1 * 4 + r1] = h01;
        basep[l0 * 4 + r0 + 1] = h10;
        basep[l1 * 4 + r1 + 1] = h11;
    }
    #pragma unroll
    for (int t = 0; t < 16; t++) {
        int i = tid + t * 256;
        int k = i >> 5, n4 = i & 31;
        float4 w = __ldg(reinterpret_cast<const float4*>(W2) + i);
        int kb = k >> 3;
        int reg = ((k & 7) >= 4) ? 1 : 0;
        int lt = k & 3;
        #pragma unroll
        for (int j = 0; j < 4; j++) {
            int n = n4 * 4 + j;
            int nb = n >> 3, nl = n & 7;
            float val = (j == 0) ? w.x : (j == 1) ? w.y : (j == 2) ? w.z : w.w;
            WsF[(((nb * 16 + kb) * 32) + nl * 4 + lt) * 2 + reg] = val;
        }
    }
    __syncthreads();

    // ---- Layer 2 ----
    #pragma unroll
    for (int n = 0; n < 8; n++)
        #pragma unroll
        for (int j = 0; j < 4; j++) c[n][j] = 0.f;

    #pragma unroll 4
    for (int kb = 0; kb < 16; kb++) {
        float4 af = *reinterpret_cast<const float4*>(&AsF[((mb * 16 + kb) * 32 + lane) * 4]);
        unsigned ah[4], al[4];
        split_tf32(af.x, ah[0], al[0]);
        split_tf32(af.y, ah[1], al[1]);
        split_tf32(af.z, ah[2], al[2]);
        split_tf32(af.w, ah[3], al[3]);
        #pragma unroll
        for (int nbl = 0; nbl < 8; nbl++) {
            int nb = nh * 8 + nbl;
            float2 bf = *reinterpret_cast<const float2*>(&WsF[((nb * 16 + kb) * 32 + lane) * 2]);
            unsigned bh0, bl0, bh1, bl1;
            split_tf32(bf.x, bh0, bl0);
            split_tf32(bf.y, bh1, bl1);
            mma_tf32(c[nbl], ah, bh0, bh1);
            mma_tf32(c[nbl], al, bh0, bh1);
            mma_tf32(c[nbl], ah, bl0, bl1);
        }
    }

    // ---- Epilogue 2: out = c + b2 ----
    int row_a = row0 + mb * 16 + g;
    int row_b = row_a + 8;
    #pragma unroll
    for (int nbl = 0; nbl < 8; nbl++) {
        int nb = nh * 8 + nbl;
        float2 bv = __ldg(reinterpret_cast<const float2*>(b2 + nb * 8 + 2 * tq));
        if (row_a < nrows) {
            float2 o = make_float2(c[nbl][0] + bv.x, c[nbl][1] + bv.y);
            *reinterpret_cast<float2*>(out + (size_t)row_a * 128 + nb * 8 + 2 * tq) = o;
        }
        if (row_b < nrows) {
            float2 o = make_float2(c[nbl][2] + bv.x, c[nbl][3] + bv.y);
            *reinterpret_cast<float2*>(out + (size_t)row_b * 128 + nb * 8 + 2 * tq) = o;
        }
    }
}

// ---------------------------------------------------------------------------
extern "C" void kernel_launch(void* const* d_in, const int* in_sizes, int n_in,
                              void* d_out, int out_size) {
    const float* x   = (const float*)d_in[0];
    const int*   ei  = (const int*)d_in[1];
    const float* ea  = (const float*)d_in[2];
    const float* eps = (const float*)d_in[3];
    const float* W1  = (const float*)d_in[4];
    const float* b1  = (const float*)d_in[5];
    const float* W2  = (const float*)d_in[6];
    const float* b2  = (const float*)d_in[7];
    float* out = (float*)d_out;

    float* aggr_p;
    cudaGetSymbolAddress((void**)&aggr_p, g_aggr);

    const int SMEM = (4 * 16 * 128 + 16 * 16 * 64) * (int)sizeof(float);  // 98304
    cudaFuncSetAttribute(mlp_tc, cudaFuncAttributeMaxDynamicSharedMemorySize, SMEM);

    // 1) slot binning of edges by dst
    zero_kernel<<<(NN + 255) / 256, 256>>>();                 // launch 1
    fill_kernel<<<(EE / 8 + 255) / 256, 256>>>(ei);           // launch 2

    // 2) gather-aggregate: warp per node
    aggr_kernel<<<NN / 8, 256>>>(x, ea);                      // launch 3

    // 3) tensor-core fused MLP (64-row tiles, 2 CTAs/SM)
    int nblk = (NN + MROWS - 1) / MROWS;
    mlp_tc<<<nblk, 256, SMEM>>>(aggr_p, x, eps, W1, b1, W2, b2, out,
                                ei, ea, NN);                  // launch 4 <- profiled
}

// round 17
// speedup vs baseline: 1.5870x; 1.5870x over previous
#include <cuda_runtime.h>

#define NN 100000
#define EE 1600000
#define DD 128
#define MAXDEG 96
#define OVF_CAP 8192
#define ROWS 96

// Scratch (allocation-free: device globals; zero-initialized at load,
// and every kernel_launch invocation restores g_fill to all-zeros)
__device__ float g_aggr[(size_t)NN * DD];
__device__ int g_fill[NN];
__device__ int2 g_perm2[(size_t)NN * MAXDEG];  // {edge, src}
__device__ int g_ovf[OVF_CAP];
__device__ int g_ovf_cnt;

// ---------------------------------------------------------------------------
// packed f32x2 helpers
// ---------------------------------------------------------------------------
__device__ __forceinline__ void fma2(unsigned long long& d, unsigned long long a,
                                     unsigned long long b) {
    asm("fma.rn.f32x2 %0, %1, %2, %3;" : "=l"(d) : "l"(a), "l"(b), "l"(d));
}
__device__ __forceinline__ unsigned long long dup2(float v) {
    unsigned long long r;
    unsigned int u = __float_as_uint(v);
    asm("mov.b64 %0, {%1, %1};" : "=l"(r) : "r"(u));
    return r;
}
__device__ __forceinline__ void unpack2(unsigned long long p, float& lo, float& hi) {
    unsigned int a, b;
    asm("mov.b64 {%0, %1}, %2;" : "=r"(a), "=r"(b) : "l"(p));
    lo = __uint_as_float(a);
    hi = __uint_as_float(b);
}
__device__ __forceinline__ void stcs4(float4* p, float4 v) {
    asm volatile("st.global.cs.v4.f32 [%0], {%1, %2, %3, %4};"
                 :: "l"(p), "f"(v.x), "f"(v.y), "f"(v.z), "f"(v.w) : "memory");
}

// ---------------------------------------------------------------------------
// Reset overflow counter only (g_fill is self-resetting in aggr_kernel).
// ---------------------------------------------------------------------------
__global__ void zero_ovf_kernel() {
    if (threadIdx.x == 0) g_ovf_cnt = 0;
}

__global__ void fill_kernel(const int* __restrict__ ei) {
    int base = (blockIdx.x * blockDim.x + threadIdx.x) * 8;
    #pragma unroll
    for (int u = 0; u < 8; u++) {
        int e = base + u;
        if (e < EE) {
            int dst = __ldg(ei + EE + e);
            int src = __ldg(ei + e);
            int pos = atomicAdd(&g_fill[dst], 1);
            if (pos < MAXDEG) {
                g_perm2[(size_t)dst * MAXDEG + pos] = make_int2(e, src);
            } else {
                int o = atomicAdd(&g_ovf_cnt, 1);
                if (o < OVF_CAP) g_ovf[o] = e;
            }
        }
    }
}

// ---------------------------------------------------------------------------
// Aggregation: warp per node. Unroll-4, 5 CTAs/SM (75% DRAM measured).
// Writes A' = sum(relu(x[src]+e)) + (1+eps)*x[node] directly, and resets
// g_fill[node] = 0 for the next invocation.
// ---------------------------------------------------------------------------
__global__ __launch_bounds__(256, 5) void aggr_kernel(const float* __restrict__ x,
                                                      const float* __restrict__ ea,
                                                      const float* __restrict__ epsp) {
    int node = blockIdx.x * 8 + (threadIdx.x >> 5);
    int lane = threadIdx.x & 31;
    int cnt = min(g_fill[node], MAXDEG);
    const int2* slots = g_perm2 + (size_t)node * MAXDEG;
    float epsv = 1.0f + __ldg(epsp);

    // A' starts as (1+eps)*x[node]
    float4 acc = __ldg(reinterpret_cast<const float4*>(x) + node * 32 + lane);
    acc.x *= epsv; acc.y *= epsv; acc.z *= epsv; acc.w *= epsv;

    for (int base = 0; base < cnt; base += 32) {
        int m = min(32, cnt - base);
        int2 es = make_int2(0, 0);
        if (lane < m) es = __ldcs(&slots[base + lane]);
        int t = 0;
        for (; t + 4 <= m; t += 4) {
            int eu[4], su[4];
            #pragma unroll
            for (int u = 0; u < 4; u++) {
                eu[u] = __shfl_sync(0xffffffffu, es.x, t + u);
                su[u] = __shfl_sync(0xffffffffu, es.y, t + u);
            }
            float4 xv[4], av[4];
            #pragma unroll
            for (int u = 0; u < 4; u++) {
                xv[u] = __ldg(reinterpret_cast<const float4*>(x) + su[u] * 32 + lane);
                av[u] = __ldcs(reinterpret_cast<const float4*>(ea) + eu[u] * 32 + lane);
            }
            #pragma unroll
            for (int u = 0; u < 4; u++) {
                acc.x += fmaxf(xv[u].x + av[u].x, 0.f);
                acc.y += fmaxf(xv[u].y + av[u].y, 0.f);
                acc.z += fmaxf(xv[u].z + av[u].z, 0.f);
                acc.w += fmaxf(xv[u].w + av[u].w, 0.f);
            }
        }
        for (; t < m; t++) {
            int et = __shfl_sync(0xffffffffu, es.x, t);
            int st = __shfl_sync(0xffffffffu, es.y, t);
            float4 xr = __ldg(reinterpret_cast<const float4*>(x) + st * 32 + lane);
            float4 ar = __ldcs(reinterpret_cast<const float4*>(ea) + et * 32 + lane);
            acc.x += fmaxf(xr.x + ar.x, 0.f);
            acc.y += fmaxf(xr.y + ar.y, 0.f);
            acc.z += fmaxf(xr.z + ar.z, 0.f);
            acc.w += fmaxf(xr.w + ar.w, 0.f);
        }
    }
    stcs4(reinterpret_cast<float4*>(g_aggr) + node * 32 + lane, acc);
    if (lane == 0) g_fill[node] = 0;  // restore invariant for next call
}

// ---------------------------------------------------------------------------
// Fused 2-layer MLP: 96-row tile, 256 threads, 6x8 micro-tile, f32x2 FMAs,
// A-fragments double-buffered across k0. A' comes pre-combined from aggr.
// ---------------------------------------------------------------------------
__device__ __forceinline__ void gemm_step(
    const float* __restrict__ As, const float* __restrict__ Ws,
    int tr, int tc, unsigned long long acc[6][4]) {
    float4 a_cur[6], a_nxt[6];
    #pragma unroll
    for (int i = 0; i < 6; i++)
        a_cur[i] = *reinterpret_cast<const float4*>(&As[(tr * 6 + i) * 128]);

    #pragma unroll
    for (int k0 = 0; k0 < 128; k0 += 4) {
        if (k0 + 4 < 128) {
            #pragma unroll
            for (int i = 0; i < 6; i++)
                a_nxt[i] = *reinterpret_cast<const float4*>(&As[(tr * 6 + i) * 128 + k0 + 4]);
        }
        #pragma unroll
        for (int kk = 0; kk < 4; kk++) {
            ulonglong2 p0 = *reinterpret_cast<const ulonglong2*>(&Ws[(k0 + kk) * 128 + tc * 4]);
            ulonglong2 p1 = *reinterpret_cast<const ulonglong2*>(&Ws[(k0 + kk) * 128 + 64 + tc * 4]);
            #pragma unroll
            for (int i = 0; i < 6; i++) {
                float av = (kk == 0) ? a_cur[i].x : (kk == 1) ? a_cur[i].y
                         : (kk == 2) ? a_cur[i].z : a_cur[i].w;
                unsigned long long a2 = dup2(av);
                fma2(acc[i][0], a2, p0.x);
                fma2(acc[i][1], a2, p0.y);
                fma2(acc[i][2], a2, p1.x);
                fma2(acc[i][3], a2, p1.y);
            }
        }
        #pragma unroll
        for (int i = 0; i < 6; i++) a_cur[i] = a_nxt[i];
    }
}

__global__ __launch_bounds__(256, 2) void mlp_fused(
    const float* __restrict__ A,
    const float* __restrict__ X,
    const float* __restrict__ W1,
    const float* __restrict__ b1,
    const float* __restrict__ W2,
    const float* __restrict__ b2,
    float* __restrict__ out,
    const int* __restrict__ ei,
    const float* __restrict__ ea,
    int nrows) {
    extern __shared__ float smem[];
    float* As = smem;               // [96][128]  (A', then h in-place)
    float* Ws = smem + ROWS * 128;  // [128][128] (W1, then W2)

    int tid = threadIdx.x;
    int row0 = blockIdx.x * ROWS;

    #pragma unroll
    for (int t = 0; t < 16; t++) {
        int i = tid + t * 256;
        reinterpret_cast<float4*>(Ws)[i] = __ldg(reinterpret_cast<const float4*>(W1) + i);
    }
    #pragma unroll
    for (int t = 0; t < 12; t++) {
        int i = tid + t * 256;
        int r = i >> 5;
        int c4 = i & 31;
        int gr = row0 + r;
        float4 v = make_float4(0.f, 0.f, 0.f, 0.f);
        if (gr < nrows)
            v = __ldcs(reinterpret_cast<const float4*>(A) + gr * 32 + c4);
        reinterpret_cast<float4*>(As)[i] = v;
    }
    __syncthreads();

    // Overflow fixup (empty for this dataset; correctness fallback).
    int nov = g_ovf_cnt;
    if (nov > 0) {
        if (nov > OVF_CAP) nov = OVF_CAP;
        int w = tid >> 5, lane = tid & 31;
        for (int o = w; o < nov; o += 8) {
            int e = g_ovf[o];
            int dst = __ldg(ei + EE + e);
            int r = dst - row0;
            if (r >= 0 && r < ROWS) {
                int src = __ldg(ei + e);
                float4 xv = __ldg(reinterpret_cast<const float4*>(X) + src * 32 + lane);
                float4 av = __ldg(reinterpret_cast<const float4*>(ea) + e * 32 + lane);
                atomicAdd(&As[r * 128 + lane * 4 + 0], fmaxf(xv.x + av.x, 0.f));
                atomicAdd(&As[r * 128 + lane * 4 + 1], fmaxf(xv.y + av.y, 0.f));
                atomicAdd(&As[r * 128 + lane * 4 + 2], fmaxf(xv.z + av.z, 0.f));
                atomicAdd(&As[r * 128 + lane * 4 + 3], fmaxf(xv.w + av.w, 0.f));
            }
        }
        __syncthreads();
    }

    int tr = tid >> 4;  // 0..15 -> rows tr*6..tr*6+5
    int tc = tid & 15;  // 0..15 -> cols {tc*4..+3} U {64+tc*4..+3}

    // ---- Layer 1 ----
    unsigned long long acc[6][4];
    #pragma unroll
    for (int i = 0; i < 6; i++)
        #pragma unroll
        for (int j = 0; j < 4; j++) acc[i][j] = 0ull;

    gemm_step(As, Ws, tr, tc, acc);
    __syncthreads();

    // Epilogue 1: h = relu(acc + b1) -> As in place; W2 -> Ws
    {
        float4 bv0 = __ldg(reinterpret_cast<const float4*>(b1) + tc);
        float4 bv1 = __ldg(reinterpret_cast<const float4*>(b1) + 16 + tc);
        #pragma unroll
        for (int i = 0; i < 6; i++) {
            float4 o0, o1;
            unpack2(acc[i][0], o0.x, o0.y);
            unpack2(acc[i][1], o0.z, o0.w);
            unpack2(acc[i][2], o1.x, o1.y);
            unpack2(acc[i][3], o1.z, o1.w);
            o0.x = fmaxf(o0.x + bv0.x, 0.f); o0.y = fmaxf(o0.y + bv0.y, 0.f);
            o0.z = fmaxf(o0.z + bv0.z, 0.f); o0.w = fmaxf(o0.w + bv0.w, 0.f);
            o1.x = fmaxf(o1.x + bv1.x, 0.f); o1.y = fmaxf(o1.y + bv1.y, 0.f);
            o1.z = fmaxf(o1.z + bv1.z, 0.f); o1.w = fmaxf(o1.w + bv1.w, 0.f);
            *reinterpret_cast<float4*>(&As[(tr * 6 + i) * 128 + tc * 4]) = o0;
            *reinterpret_cast<float4*>(&As[(tr * 6 + i) * 128 + 64 + tc * 4]) = o1;
        }
        #pragma unroll
        for (int t = 0; t < 16; t++) {
            int i = tid + t * 256;
            reinterpret_cast<float4*>(Ws)[i] = __ldg(reinterpret_cast<const float4*>(W2) + i);
        }
    }
    __syncthreads();

    // ---- Layer 2 ----
    #pragma unroll
    for (int i = 0; i < 6; i++)
        #pragma unroll
        for (int j = 0; j < 4; j++) acc[i][j] = 0ull;

    gemm_step(As, Ws, tr, tc, acc);

    float4 bv0 = __ldg(reinterpret_cast<const float4*>(b2) + tc);
    float4 bv1 = __ldg(reinterpret_cast<const float4*>(b2) + 16 + tc);
    #pragma unroll
    for (int i = 0; i < 6; i++) {
        int gr = row0 + tr * 6 + i;
        if (gr < nrows) {
            float4 o0, o1;
            unpack2(acc[i][0], o0.x, o0.y);
            unpack2(acc[i][1], o0.z, o0.w);
            unpack2(acc[i][2], o1.x, o1.y);
            unpack2(acc[i][3], o1.z, o1.w);
            o0.x += bv0.x; o0.y += bv0.y; o0.z += bv0.z; o0.w += bv0.w;
            o1.x += bv1.x; o1.y += bv1.y; o1.z += bv1.z; o1.w += bv1.w;
            reinterpret_cast<float4*>(out)[gr * 32 + tc] = o0;
            reinterpret_cast<float4*>(out)[gr * 32 + 16 + tc] = o1;
        }
    }
}

// ---------------------------------------------------------------------------
extern "C" void kernel_launch(void* const* d_in, const int* in_sizes, int n_in,
                              void* d_out, int out_size) {
    const float* x   = (const float*)d_in[0];
    const int*   ei  = (const int*)d_in[1];
    const float* ea  = (const float*)d_in[2];
    const float* eps = (const float*)d_in[3];
    const float* W1  = (const float*)d_in[4];
    const float* b1  = (const float*)d_in[5];
    const float* W2  = (const float*)d_in[6];
    const float* b2  = (const float*)d_in[7];
    float* out = (float*)d_out;

    float* aggr_p;
    cudaGetSymbolAddress((void**)&aggr_p, g_aggr);

    const int SMEM = (ROWS * 128 + 128 * 128) * (int)sizeof(float);  // 114688
    cudaFuncSetAttribute(mlp_fused, cudaFuncAttributeMaxDynamicSharedMemorySize, SMEM);

    // 1) reset overflow counter (g_fill self-resets in aggr)
    zero_ovf_kernel<<<1, 32>>>();                             // launch 1
    // 2) slot binning of edges by dst
    fill_kernel<<<(EE / 8 + 255) / 256, 256>>>(ei);           // launch 2
    // 3) gather-aggregate + (1+eps)x, warp per node
    aggr_kernel<<<NN / 8, 256>>>(x, ea, eps);                 // launch 3
    // 4) fused 2-layer MLP
    int nblk = (NN + ROWS - 1) / ROWS;
    mlp_fused<<<nblk, 256, SMEM>>>(aggr_p, x, W1, b1, W2, b2, out,
                                   ei, ea, NN);               // launch 4 <- profiled
}